// round 5
// baseline (speedup 1.0000x reference)
#include <cuda_runtime.h>
#include <cuda_bf16.h>
#include <cstdint>
#include <math.h>

// ---------------- Problem constants ----------------
#define VOCAB 32000
#define DMODEL 1024
#define DEPTH 6
#define NHEAD 16
#define SEQL 1024
#define BATCH 2
#define LRANK 16
#define HIDDEN 4096
#define HEADDIM 64
#define NTOK (BATCH * SEQL)          // 2048
#define SCALING 0.5f                  // 8.0 / 16

// ---------------- Scratch (device globals; no allocation allowed) -------------
static __device__ float g_x  [NTOK * DMODEL];
static __device__ float g_h  [NTOK * DMODEL];
static __device__ float g_qkv[NTOK * 3 * DMODEL];
static __device__ float g_o  [NTOK * DMODEL];
static __device__ float g_ff [NTOK * HIDDEN];
static __device__ float g_scores[(long)BATCH * NHEAD * SEQL * SEQL]; // 128 MB
static __device__ float g_wqkv[DEPTH * 3 * DMODEL * DMODEL];
static __device__ float g_bqkv[DEPTH * 3 * DMODEL];
static __device__ float g_wo  [DEPTH * DMODEL * DMODEL];

// ---------------- small PTX helpers (baseline ISA only) ----------------
__device__ __forceinline__ uint32_t f2tf(float f) {
    uint32_t u;
    asm("cvt.rna.tf32.f32 %0, %1;" : "=r"(u) : "f"(f));
    return u;
}
__device__ __forceinline__ void mma_tf32(float* d, const uint32_t* a,
                                         const uint32_t* b) {
    asm volatile(
        "mma.sync.aligned.m16n8k8.row.col.f32.tf32.tf32.f32 "
        "{%0,%1,%2,%3}, {%4,%5,%6,%7}, {%8,%9}, {%0,%1,%2,%3};"
        : "+f"(d[0]), "+f"(d[1]), "+f"(d[2]), "+f"(d[3])
        : "r"(a[0]), "r"(a[1]), "r"(a[2]), "r"(a[3]), "r"(b[0]), "r"(b[1]));
}

// ---------------- helpers ----------------
__device__ __forceinline__ float gelu_exact(float x) {
    return 0.5f * x * (1.0f + erff(x * 0.70710678118654752440f));
}

// ---------------- W_eff = W + 0.5 * A @ B  (LoRA fold, float4) --------------
// Writes into out[layer * outLS + outOff + rem]
__global__ void weff_kernel(const float* __restrict__ W,
                            const float* __restrict__ Am,   // [DEPTH, D, R]
                            const float* __restrict__ Bm,   // [DEPTH, R, D]
                            float* __restrict__ out,
                            long outLS, long outOff) {
    long e4 = (long)blockIdx.x * 256 + threadIdx.x;   // DEPTH*D*D/4 total
    const int DD4 = DMODEL * DMODEL / 4;
    int layer = (int)(e4 / DD4);
    int rem4  = (int)(e4 % DD4);
    int orow  = rem4 / (DMODEL / 4);
    int ic4   = (rem4 % (DMODEL / 4)) * 4;
    const float* a  = Am + (long)layer * DMODEL * LRANK + (long)orow * LRANK;
    const float* bb = Bm + (long)layer * LRANK * DMODEL + ic4;
    float4 s = make_float4(0.f, 0.f, 0.f, 0.f);
#pragma unroll
    for (int r = 0; r < LRANK; r++) {
        float4 bv = *reinterpret_cast<const float4*>(bb + (long)r * DMODEL);
        float av = a[r];
        s.x += av * bv.x; s.y += av * bv.y; s.z += av * bv.z; s.w += av * bv.w;
    }
    float4 wv = *reinterpret_cast<const float4*>(
        W + (long)layer * DMODEL * DMODEL + rem4 * 4);
    wv.x += SCALING * s.x; wv.y += SCALING * s.y;
    wv.z += SCALING * s.z; wv.w += SCALING * s.w;
    *reinterpret_cast<float4*>(
        out + (long)layer * outLS + outOff + rem4 * 4) = wv;
}

// ---------------- bias concat for fused QKV ----------------
__global__ void bias_concat_kernel(const float* __restrict__ bq,
                                   const float* __restrict__ bk,
                                   const float* __restrict__ bv,
                                   float* __restrict__ out) {
    int e = blockIdx.x * 256 + threadIdx.x;       // DEPTH * 3 * D
    int layer = e / (3 * DMODEL);
    int r = e % (3 * DMODEL);
    const float* src = (r < DMODEL) ? bq : (r < 2 * DMODEL ? bk : bv);
    out[e] = src[layer * DMODEL + (r % DMODEL)];
}

// ---------------- Embedding + phase rotator ----------------
__global__ void embed_kernel(const int* __restrict__ idx,
                             const float* __restrict__ tok,
                             const float* __restrict__ pos,
                             const float* __restrict__ phase,
                             float* __restrict__ x) {
    int row = blockIdx.x;
    int l   = row % SEQL;
    int t   = idx[row];
    for (int d = threadIdx.x; d < DMODEL; d += blockDim.x) {
        float phi = tanhf(phase[d]) * 3.14159265358979323846f;
        float fac = cosf(phi) - sinf(phi);
        x[(long)row * DMODEL + d] =
            (tok[(long)t * DMODEL + d] + pos[(long)l * DMODEL + d]) * fac;
    }
}

// ---------------- LayerNorm ----------------
__global__ void ln_kernel(const float* __restrict__ x,
                          const float* __restrict__ w,
                          const float* __restrict__ b,
                          float* __restrict__ o) {
    int row = blockIdx.x;
    const float* xr = x + (long)row * DMODEL;
    int tid = threadIdx.x;
    float s = 0.f, s2 = 0.f;
    float v[4];
#pragma unroll
    for (int j = 0; j < 4; j++) {
        v[j] = xr[tid + 256 * j];
        s += v[j]; s2 += v[j] * v[j];
    }
    __shared__ float r1[256], r2[256];
    r1[tid] = s; r2[tid] = s2;
    __syncthreads();
    for (int off = 128; off > 0; off >>= 1) {
        if (tid < off) { r1[tid] += r1[tid + off]; r2[tid] += r2[tid + off]; }
        __syncthreads();
    }
    float mean = r1[0] * (1.0f / DMODEL);
    float var  = r2[0] * (1.0f / DMODEL) - mean * mean;
    float rstd = rsqrtf(var + 1e-5f);
    float* orow = o + (long)row * DMODEL;
#pragma unroll
    for (int j = 0; j < 4; j++) {
        int d = tid + 256 * j;
        orow[d] = (v[j] - mean) * rstd * w[d] + b[d];
    }
}

// ---------------- Causal softmax ----------------
// zero-fill only to the end of the diagonal 128-tile: AV's K-limit never
// reads beyond it, and tiles right of the diagonal are never written.
__global__ void softmax_kernel(float* __restrict__ sc) {
    long row = blockIdx.x;
    int l = (int)(row % SEQL);
    float* s = sc + row * (long)SEQL;
    int tid = threadIdx.x;
    __shared__ float red[256];

    const float scale = 0.125f;   // HEADDIM^-0.5
    float mx = -3.4e38f;
    for (int j = tid; j <= l; j += 256) mx = fmaxf(mx, s[j]);
    red[tid] = mx;
    __syncthreads();
    for (int off = 128; off > 0; off >>= 1) {
        if (tid < off) red[tid] = fmaxf(red[tid], red[tid + off]);
        __syncthreads();
    }
    mx = red[0] * scale;
    __syncthreads();

    float sum = 0.f;
    for (int j = tid; j <= l; j += 256) {
        float e = __expf(s[j] * scale - mx);
        s[j] = e;
        sum += e;
    }
    red[tid] = sum;
    __syncthreads();
    for (int off = 128; off > 0; off >>= 1) {
        if (tid < off) red[tid] += red[tid + off];
        __syncthreads();
    }
    float inv = 1.0f / red[0];
    for (int j = tid; j <= l; j += 256) s[j] *= inv;
    int tile_end = ((l >> 7) + 1) << 7;
    for (int j = l + 1 + tid; j < tile_end; j += 256) s[j] = 0.0f;
}

// ---------------- tf32 mma.sync GEMM (v2: cvt at store, reg pipeline) -------
// C[m,n] = sum_k A[m*lda+k] * B[n*sBn + k*sBk]  (+bias)(gelu)(+residual)
// flags: 1 = gelu, 4 = causal tile-skip, 8 = causal K-limit, 16 = grid swap
// BM=128, BK=32; 8 warps 2x4; warp tile 64 x (BN/4).
template<int BN>
__global__ __launch_bounds__(256)
void mma_gemm(const float* __restrict__ A, int lda,
              const float* __restrict__ Bp, long sBn, long sBk,
              const float* __restrict__ bias,
              const float* __restrict__ res, int ldr,
              float* __restrict__ C, int ldc,
              int K, int flags, int batchH,
              long aO, long aI, long bO, long bI, long cO, long cI) {
    constexpr int BM = 128, BK = 32, LDSS = BK + 4;       // 36 words/row
    extern __shared__ uint32_t smu[];
    uint32_t* As = smu;                                    // [2][BM][36]
    uint32_t* Bs = smu + 2 * BM * LDSS;                    // [2][BN][36]

    if (batchH > 0) {
        int z = blockIdx.z;
        A  += (z / batchH) * aO + (z % batchH) * aI;
        Bp += (z / batchH) * bO + (z % batchH) * bI;
        C  += (z / batchH) * cO + (z % batchH) * cI;
    }
    int bx = blockIdx.x, by = blockIdx.y;
    if (flags & 16) { int t = bx; bx = by; by = t; }
    const int bm0 = by * BM;
    const int bn0 = bx * BN;
    if (flags & 4) { if (bn0 > bm0 + BM - 1) return; }
    int Keff = K;
    if (flags & 8) Keff = min(K, bm0 + BM);
    const int T = Keff / BK;

    const int tid  = threadIdx.x;
    const int w    = tid >> 5;
    const int lane = tid & 31;
    const int wm = w >> 2, wn = w & 3;
    const int g = lane >> 2, tig = lane & 3;
    constexpr int WN = BN / 4;
    constexpr int NT = WN / 8;
    constexpr int BF4 = BN / 32;          // B float4 per thread per tile

    float acc[4][NT][4];
#pragma unroll
    for (int i = 0; i < 4; i++)
#pragma unroll
        for (int j = 0; j < NT; j++)
#pragma unroll
            for (int r = 0; r < 4; r++) acc[i][j][r] = 0.0f;

    const bool bK = (sBk == 1);

    float4 ra[4], rb[BF4];

    auto ldg_tile = [&](int it) {
        const int k0 = it * BK;
#pragma unroll
        for (int t = 0; t < 4; t++) {
            int vv = tid + t * 256;
            int m = vv >> 3, j = vv & 7;
            ra[t] = *reinterpret_cast<const float4*>(
                A + (long)(bm0 + m) * lda + k0 + j * 4);
        }
        if (bK) {
#pragma unroll
            for (int t = 0; t < BF4; t++) {
                int vv = tid + t * 256;
                int n = vv >> 3, j = vv & 7;
                rb[t] = *reinterpret_cast<const float4*>(
                    Bp + (long)(bn0 + n) * sBn + k0 + j * 4);
            }
        } else {
#pragma unroll
            for (int t = 0; t < BF4; t++) {
                int vv = tid + t * 256;
                int kk = vv / (BN / 4), nq = vv % (BN / 4);
                rb[t] = *reinterpret_cast<const float4*>(
                    Bp + (long)(k0 + kk) * sBk + bn0 + nq * 4);
            }
        }
    };

    auto sts_tile = [&](int buf) {
#pragma unroll
        for (int t = 0; t < 4; t++) {
            int vv = tid + t * 256;
            int m = vv >> 3, j = vv & 7;
            uint4 u;
            u.x = f2tf(ra[t].x); u.y = f2tf(ra[t].y);
            u.z = f2tf(ra[t].z); u.w = f2tf(ra[t].w);
            *reinterpret_cast<uint4*>(&As[buf * BM * LDSS + m * LDSS + j * 4]) = u;
        }
        if (bK) {
#pragma unroll
            for (int t = 0; t < BF4; t++) {
                int vv = tid + t * 256;
                int n = vv >> 3, j = vv & 7;
                uint4 u;
                u.x = f2tf(rb[t].x); u.y = f2tf(rb[t].y);
                u.z = f2tf(rb[t].z); u.w = f2tf(rb[t].w);
                *reinterpret_cast<uint4*>(&Bs[buf * BN * LDSS + n * LDSS + j * 4]) = u;
            }
        } else {
#pragma unroll
            for (int t = 0; t < BF4; t++) {
                int vv = tid + t * 256;
                int kk = vv / (BN / 4), nq = vv % (BN / 4);
                uint32_t* bb = &Bs[buf * BN * LDSS + (nq * 4) * LDSS + kk];
                bb[0 * LDSS] = f2tf(rb[t].x);
                bb[1 * LDSS] = f2tf(rb[t].y);
                bb[2 * LDSS] = f2tf(rb[t].z);
                bb[3 * LDSS] = f2tf(rb[t].w);
            }
        }
    };

    ldg_tile(0);
    sts_tile(0);
    __syncthreads();

    for (int it = 0; it < T; it++) {
        const int buf = it & 1;
        if (it + 1 < T) ldg_tile(it + 1);

        const uint32_t* Ab = As + buf * BM * LDSS;
        const uint32_t* Bb = Bs + buf * BN * LDSS;
#pragma unroll
        for (int ks = 0; ks < 4; ks++) {
            uint32_t af[4][4];
#pragma unroll
            for (int i = 0; i < 4; i++) {
                const uint32_t* ap = Ab + (wm * 64 + i * 16) * LDSS + ks * 8;
                af[i][0] = ap[g * LDSS + tig];
                af[i][1] = ap[(g + 8) * LDSS + tig];
                af[i][2] = ap[g * LDSS + tig + 4];
                af[i][3] = ap[(g + 8) * LDSS + tig + 4];
            }
            uint32_t bf[NT][2];
#pragma unroll
            for (int j = 0; j < NT; j++) {
                const uint32_t* bp = Bb + (wn * WN + j * 8 + g) * LDSS + ks * 8;
                bf[j][0] = bp[tig];
                bf[j][1] = bp[tig + 4];
            }
#pragma unroll
            for (int i = 0; i < 4; i++)
#pragma unroll
                for (int j = 0; j < NT; j++)
                    mma_tf32(acc[i][j], af[i], bf[j]);
        }

        if (it + 1 < T) sts_tile(buf ^ 1);
        __syncthreads();
    }

    // epilogue -----------------------------------------------------------
#pragma unroll
    for (int i = 0; i < 4; i++) {
        int r0 = bm0 + wm * 64 + i * 16 + g;
#pragma unroll
        for (int j = 0; j < NT; j++) {
            int c = bn0 + wn * WN + j * 8 + tig * 2;
            float e00 = acc[i][j][0], e01 = acc[i][j][1];
            float e10 = acc[i][j][2], e11 = acc[i][j][3];
            if (bias) {
                float2 bb = *reinterpret_cast<const float2*>(bias + c);
                e00 += bb.x; e01 += bb.y; e10 += bb.x; e11 += bb.y;
            }
            if (flags & 1) {
                e00 = gelu_exact(e00); e01 = gelu_exact(e01);
                e10 = gelu_exact(e10); e11 = gelu_exact(e11);
            }
            if (res) {
                float2 ra2 = *reinterpret_cast<const float2*>(
                    res + (long)r0 * ldr + c);
                float2 rb2 = *reinterpret_cast<const float2*>(
                    res + (long)(r0 + 8) * ldr + c);
                e00 += ra2.x; e01 += ra2.y; e10 += rb2.x; e11 += rb2.y;
            }
            *reinterpret_cast<float2*>(C + (long)r0 * ldc + c) =
                make_float2(e00, e01);
            *reinterpret_cast<float2*>(C + (long)(r0 + 8) * ldc + c) =
                make_float2(e10, e11);
        }
    }
}

// ---------------- host-side launch helpers ----------------
static constexpr int SMEM128 = (2 * 128 * 36 + 2 * 128 * 36) * 4;  // 73728
static constexpr int SMEM64  = (2 * 128 * 36 + 2 * 64  * 36) * 4;  // 55296

static void tgemm128(const float* A, int lda, const float* B, long sBn, long sBk,
                     const float* bias, const float* res, int ldr,
                     float* C, int ldc, int M, int N, int K, int flags,
                     int batch = 1, int batchH = 0,
                     long aO = 0, long aI = 0, long bO = 0, long bI = 0,
                     long cO = 0, long cI = 0) {
    dim3 gdim;
    if (flags & 16) gdim = dim3(M / 128, N / 128, batch);
    else            gdim = dim3(N / 128, M / 128, batch);
    mma_gemm<128><<<gdim, 256, SMEM128>>>(A, lda, B, sBn, sBk, bias, res, ldr,
                                          C, ldc, K, flags, batchH,
                                          aO, aI, bO, bI, cO, cI);
}
static void tgemm64(const float* A, int lda, const float* B, long sBn, long sBk,
                    const float* bias, const float* res, int ldr,
                    float* C, int ldc, int M, int N, int K, int flags,
                    int batch = 1, int batchH = 0,
                    long aO = 0, long aI = 0, long bO = 0, long bI = 0,
                    long cO = 0, long cI = 0) {
    dim3 gdim(N / 64, M / 128, batch);
    mma_gemm<64><<<gdim, 256, SMEM64>>>(A, lda, B, sBn, sBk, bias, res, ldr,
                                        C, ldc, K, flags, batchH,
                                        aO, aI, bO, bI, cO, cI);
}

// ---------------- entry point ----------------
extern "C" void kernel_launch(void* const* d_in, const int* in_sizes, int n_in,
                              void* d_out, int out_size) {
    // dict order: 0 idx, 1 tok, 2 pos, 3 phase, 4 ln1_w, 5 ln1_b, 6 ln2_w, 7 ln2_b,
    // 8..23 {W,b,B,A} x {q,k,v,o}, 24 W1, 25 b1, 26 W2, 27 b2, 28 lnf_w, 29 lnf_b, 30 head_W
    const int*   idx   = (const int*)  d_in[0];
    const float* tok   = (const float*)d_in[1];
    const float* pos   = (const float*)d_in[2];
    const float* phase = (const float*)d_in[3];
    const float* ln1w  = (const float*)d_in[4];
    const float* ln1b  = (const float*)d_in[5];

    const float *ln2w, *ln2b;
    int wbase;
    if (in_sizes[6] == DEPTH * DMODEL) {        // dict order
        ln2w = (const float*)d_in[6];
        ln2b = (const float*)d_in[7];
        wbase = 8;
    } else {                                     // signature order fallback
        ln2w = (const float*)d_in[22];
        ln2b = (const float*)d_in[23];
        wbase = 6;
    }
    const float* Wq = (const float*)d_in[wbase + 0];
    const float* bq = (const float*)d_in[wbase + 1];
    const float* Bq = (const float*)d_in[wbase + 2];
    const float* Aq = (const float*)d_in[wbase + 3];
    const float* Wk = (const float*)d_in[wbase + 4];
    const float* bk = (const float*)d_in[wbase + 5];
    const float* Bk = (const float*)d_in[wbase + 6];
    const float* Ak = (const float*)d_in[wbase + 7];
    const float* Wv = (const float*)d_in[wbase + 8];
    const float* bv = (const float*)d_in[wbase + 9];
    const float* Bv = (const float*)d_in[wbase + 10];
    const float* Av = (const float*)d_in[wbase + 11];
    const float* Wo = (const float*)d_in[wbase + 12];
    const float* bo = (const float*)d_in[wbase + 13];
    const float* Bo = (const float*)d_in[wbase + 14];
    const float* Ao = (const float*)d_in[wbase + 15];
    const float* W1 = (const float*)d_in[24];
    const float* b1 = (const float*)d_in[25];
    const float* W2 = (const float*)d_in[26];
    const float* b2 = (const float*)d_in[27];
    const float* lnfw = (const float*)d_in[28];
    const float* lnfb = (const float*)d_in[29];
    const float* headW = (const float*)d_in[30];
    float* out = (float*)d_out;

    float *x, *h, *qkv, *o, *ff, *sc, *wqkv, *bqkv, *wo;
    cudaGetSymbolAddress((void**)&x,   g_x);
    cudaGetSymbolAddress((void**)&h,   g_h);
    cudaGetSymbolAddress((void**)&qkv, g_qkv);
    cudaGetSymbolAddress((void**)&o,   g_o);
    cudaGetSymbolAddress((void**)&ff,  g_ff);
    cudaGetSymbolAddress((void**)&sc,  g_scores);
    cudaGetSymbolAddress((void**)&wqkv, g_wqkv);
    cudaGetSymbolAddress((void**)&bqkv, g_bqkv);
    cudaGetSymbolAddress((void**)&wo,  g_wo);

    cudaFuncSetAttribute(mma_gemm<128>,
                         cudaFuncAttributeMaxDynamicSharedMemorySize, SMEM128);
    cudaFuncSetAttribute(mma_gemm<64>,
                         cudaFuncAttributeMaxDynamicSharedMemorySize, SMEM64);

    const int D = DMODEL, L = SEQL, Hh = NHEAD, HD = HEADDIM;
    const long DD = (long)D * D;
    const long LL = (long)L * L;
    const long LD3 = (long)L * 3 * D;

    // 1) fold LoRA into effective weights (QKV concatenated)
    {
        int nblk = (int)(DEPTH * DD / 4 / 256);
        weff_kernel<<<nblk, 256>>>(Wq, Aq, Bq, wqkv, 3 * DD, 0);
        weff_kernel<<<nblk, 256>>>(Wk, Ak, Bk, wqkv, 3 * DD, DD);
        weff_kernel<<<nblk, 256>>>(Wv, Av, Bv, wqkv, 3 * DD, 2 * DD);
        weff_kernel<<<nblk, 256>>>(Wo, Ao, Bo, wo, DD, 0);
        bias_concat_kernel<<<DEPTH * 3 * D / 256, 256>>>(bq, bk, bv, bqkv);
    }

    // 2) embedding + phase rotator
    embed_kernel<<<NTOK, 256>>>(idx, tok, pos, phase, x);

    // 3) transformer layers
    for (int i = 0; i < DEPTH; i++) {
        const float* wqkv_i = wqkv + (long)i * 3 * DD;
        const float* woi    = wo + (long)i * DD;

        ln_kernel<<<NTOK, 256>>>(x, ln1w + i * D, ln1b + i * D, h);

        // fused QKV: qkv[NTOK, 3072]
        tgemm128(h, D, wqkv_i, D, 1, bqkv + (long)i * 3 * D, nullptr, 0,
                 qkv, 3 * D, NTOK, 3 * D, D, 0);

        // scores[z][l][j] = q . k  (batched over B*H, causal tile-skip)
        tgemm128(qkv, 3 * D, qkv + D, 3 * D, 1, nullptr, nullptr, 0, sc, L,
                 L, L, HD, /*flags=*/4,
                 BATCH * Hh, Hh,
                 LD3, HD, LD3, HD,
                 (long)Hh * LL, LL);

        softmax_kernel<<<BATCH * Hh * L, 256>>>(sc);

        // o = attn @ V (batched, causal K-limit); B elem (n,k') = v[k'*3D + n]
        tgemm64(sc, L, qkv + 2 * D, 1, 3 * D, nullptr, nullptr, 0, o, D,
                L, HD, L, /*flags=*/8,
                BATCH * Hh, Hh,
                (long)Hh * LL, LL,
                LD3, HD,
                (long)L * D, HD);

        // x = x + o @ Wo_eff^T + bo
        tgemm128(o, D, woi, D, 1, bo + i * D, x, D, x, D, NTOK, D, D, 0);

        ln_kernel<<<NTOK, 256>>>(x, ln2w + i * D, ln2b + i * D, h);

        // ff = gelu(h @ W1^T + b1)
        tgemm128(h, D, W1 + (long)i * HIDDEN * D, D, 1, b1 + i * HIDDEN,
                 nullptr, 0, ff, HIDDEN, NTOK, HIDDEN, D, /*flags=*/1);
        // x = x + ff @ W2^T + b2
        tgemm128(ff, HIDDEN, W2 + (long)i * D * HIDDEN, HIDDEN, 1, b2 + i * D,
                 x, D, x, D, NTOK, D, HIDDEN, 0);
    }

    // 4) final LN + LM head (grid-swapped: M-blocks vary fastest for L2 B reuse)
    ln_kernel<<<NTOK, 256>>>(x, lnfw, lnfb, h);
    tgemm128(h, D, headW, D, 1, nullptr, nullptr, 0, out, VOCAB,
             NTOK, VOCAB, D, /*flags=*/16);
}

// round 6
// speedup vs baseline: 1.1531x; 1.1531x over previous
#include <cuda_runtime.h>
#include <cuda_bf16.h>
#include <cstdint>
#include <math.h>

// ---------------- Problem constants ----------------
#define VOCAB 32000
#define DMODEL 1024
#define DEPTH 6
#define NHEAD 16
#define SEQL 1024
#define BATCH 2
#define LRANK 16
#define HIDDEN 4096
#define HEADDIM 64
#define NTOK (BATCH * SEQL)          // 2048
#define SCALING 0.5f                  // 8.0 / 16

// ---------------- Scratch (device globals; no allocation allowed) -------------
static __device__ float g_x  [NTOK * DMODEL];
static __device__ float g_h  [NTOK * DMODEL];
static __device__ float g_qkv[NTOK * 3 * DMODEL];
static __device__ float g_o  [NTOK * DMODEL];
static __device__ float g_ff [NTOK * HIDDEN];
static __device__ float g_scores[(long)BATCH * NHEAD * SEQL * SEQL]; // 128 MB
static __device__ float g_wqkv[DEPTH * 3 * DMODEL * DMODEL];
static __device__ float g_bqkv[DEPTH * 3 * DMODEL];
static __device__ float g_wo  [DEPTH * DMODEL * DMODEL];

// ---------------- small PTX helpers (baseline ISA only) ----------------
__device__ __forceinline__ uint32_t smem_u32(const void* p) {
    uint32_t a;
    asm("{ .reg .u64 t; cvta.to.shared.u64 t, %1; cvt.u32.u64 %0, t; }"
        : "=r"(a) : "l"(p));
    return a;
}
__device__ __forceinline__ void cp16(uint32_t dst, const void* src) {
    asm volatile("cp.async.cg.shared.global [%0], [%1], 16;"
                 :: "r"(dst), "l"(src));
}
#define CP_COMMIT() asm volatile("cp.async.commit_group;" ::: "memory")
#define CP_WAIT1()  asm volatile("cp.async.wait_group 1;"  ::: "memory")
#define CP_WAIT0()  asm volatile("cp.async.wait_group 0;"  ::: "memory")

__device__ __forceinline__ uint32_t f2tf(float f) {
    uint32_t u;
    asm("cvt.rna.tf32.f32 %0, %1;" : "=r"(u) : "f"(f));
    return u;
}
__device__ __forceinline__ void mma_tf32(float* d, const uint32_t* a,
                                         const uint32_t* b) {
    asm volatile(
        "mma.sync.aligned.m16n8k8.row.col.f32.tf32.tf32.f32 "
        "{%0,%1,%2,%3}, {%4,%5,%6,%7}, {%8,%9}, {%0,%1,%2,%3};"
        : "+f"(d[0]), "+f"(d[1]), "+f"(d[2]), "+f"(d[3])
        : "r"(a[0]), "r"(a[1]), "r"(a[2]), "r"(a[3]), "r"(b[0]), "r"(b[1]));
}

// ---------------- helpers ----------------
__device__ __forceinline__ float gelu_exact(float x) {
    return 0.5f * x * (1.0f + erff(x * 0.70710678118654752440f));
}

// ---------------- W_eff = W + 0.5 * A @ B  (LoRA fold, float4) --------------
__global__ void weff_kernel(const float* __restrict__ W,
                            const float* __restrict__ Am,   // [DEPTH, D, R]
                            const float* __restrict__ Bm,   // [DEPTH, R, D]
                            float* __restrict__ out,
                            long outLS, long outOff) {
    long e4 = (long)blockIdx.x * 256 + threadIdx.x;   // DEPTH*D*D/4 total
    const int DD4 = DMODEL * DMODEL / 4;
    int layer = (int)(e4 / DD4);
    int rem4  = (int)(e4 % DD4);
    int orow  = rem4 / (DMODEL / 4);
    int ic4   = (rem4 % (DMODEL / 4)) * 4;
    const float* a  = Am + (long)layer * DMODEL * LRANK + (long)orow * LRANK;
    const float* bb = Bm + (long)layer * LRANK * DMODEL + ic4;
    float4 s = make_float4(0.f, 0.f, 0.f, 0.f);
#pragma unroll
    for (int r = 0; r < LRANK; r++) {
        float4 bv = *reinterpret_cast<const float4*>(bb + (long)r * DMODEL);
        float av = a[r];
        s.x += av * bv.x; s.y += av * bv.y; s.z += av * bv.z; s.w += av * bv.w;
    }
    float4 wv = *reinterpret_cast<const float4*>(
        W + (long)layer * DMODEL * DMODEL + rem4 * 4);
    wv.x += SCALING * s.x; wv.y += SCALING * s.y;
    wv.z += SCALING * s.z; wv.w += SCALING * s.w;
    *reinterpret_cast<float4*>(
        out + (long)layer * outLS + outOff + rem4 * 4) = wv;
}

// ---------------- bias concat for fused QKV ----------------
__global__ void bias_concat_kernel(const float* __restrict__ bq,
                                   const float* __restrict__ bk,
                                   const float* __restrict__ bv,
                                   float* __restrict__ out) {
    int e = blockIdx.x * 256 + threadIdx.x;       // DEPTH * 3 * D
    int layer = e / (3 * DMODEL);
    int r = e % (3 * DMODEL);
    const float* src = (r < DMODEL) ? bq : (r < 2 * DMODEL ? bk : bv);
    out[e] = src[layer * DMODEL + (r % DMODEL)];
}

// ---------------- Embedding + phase rotator ----------------
__global__ void embed_kernel(const int* __restrict__ idx,
                             const float* __restrict__ tok,
                             const float* __restrict__ pos,
                             const float* __restrict__ phase,
                             float* __restrict__ x) {
    int row = blockIdx.x;
    int l   = row % SEQL;
    int t   = idx[row];
    for (int d = threadIdx.x; d < DMODEL; d += blockDim.x) {
        float phi = tanhf(phase[d]) * 3.14159265358979323846f;
        float fac = cosf(phi) - sinf(phi);
        x[(long)row * DMODEL + d] =
            (tok[(long)t * DMODEL + d] + pos[(long)l * DMODEL + d]) * fac;
    }
}

// ---------------- LayerNorm ----------------
__global__ void ln_kernel(const float* __restrict__ x,
                          const float* __restrict__ w,
                          const float* __restrict__ b,
                          float* __restrict__ o) {
    int row = blockIdx.x;
    const float* xr = x + (long)row * DMODEL;
    int tid = threadIdx.x;
    float s = 0.f, s2 = 0.f;
    float v[4];
#pragma unroll
    for (int j = 0; j < 4; j++) {
        v[j] = xr[tid + 256 * j];
        s += v[j]; s2 += v[j] * v[j];
    }
    __shared__ float r1[256], r2[256];
    r1[tid] = s; r2[tid] = s2;
    __syncthreads();
    for (int off = 128; off > 0; off >>= 1) {
        if (tid < off) { r1[tid] += r1[tid + off]; r2[tid] += r2[tid + off]; }
        __syncthreads();
    }
    float mean = r1[0] * (1.0f / DMODEL);
    float var  = r2[0] * (1.0f / DMODEL) - mean * mean;
    float rstd = rsqrtf(var + 1e-5f);
    float* orow = o + (long)row * DMODEL;
#pragma unroll
    for (int j = 0; j < 4; j++) {
        int d = tid + 256 * j;
        orow[d] = (v[j] - mean) * rstd * w[d] + b[d];
    }
}

// ---------------- Causal softmax ----------------
// zero-fill only to the end of the diagonal 128-tile: AV's K-limit never
// reads beyond it, and tiles right of the diagonal are never written.
__global__ void softmax_kernel(float* __restrict__ sc) {
    long row = blockIdx.x;
    int l = (int)(row % SEQL);
    float* s = sc + row * (long)SEQL;
    int tid = threadIdx.x;
    __shared__ float red[256];

    const float scale = 0.125f;   // HEADDIM^-0.5
    float mx = -3.4e38f;
    for (int j = tid; j <= l; j += 256) mx = fmaxf(mx, s[j]);
    red[tid] = mx;
    __syncthreads();
    for (int off = 128; off > 0; off >>= 1) {
        if (tid < off) red[tid] = fmaxf(red[tid], red[tid + off]);
        __syncthreads();
    }
    mx = red[0] * scale;
    __syncthreads();

    float sum = 0.f;
    for (int j = tid; j <= l; j += 256) {
        float e = __expf(s[j] * scale - mx);
        s[j] = e;
        sum += e;
    }
    red[tid] = sum;
    __syncthreads();
    for (int off = 128; off > 0; off >>= 1) {
        if (tid < off) red[tid] += red[tid + off];
        __syncthreads();
    }
    float inv = 1.0f / red[0];
    for (int j = tid; j <= l; j += 256) s[j] *= inv;
    int tile_end = ((l >> 7) + 1) << 7;
    for (int j = l + 1 + tid; j < tile_end; j += 256) s[j] = 0.0f;
}

// ---------------- tf32 mma.sync GEMM (R4 core: cp.async + cvt in loop) ------
// C[m,n] = sum_k A[m*lda+k] * B[n*sBn + k*sBk]  (+bias)(gelu)(+residual)
// flags: 1 = gelu, 4 = causal tile-skip, 8 = causal K-limit, 16 = grid swap
// BM=128, BK=32; 8 warps in 2x4, warp tile 64 x (BN/4).
template<int BN>
__global__ __launch_bounds__(256)
void mma_gemm(const float* __restrict__ A, int lda,
              const float* __restrict__ Bp, long sBn, long sBk,
              const float* __restrict__ bias,
              const float* __restrict__ res, int ldr,
              float* __restrict__ C, int ldc,
              int K, int flags, int batchH,
              long aO, long aI, long bO, long bI, long cO, long cI) {
    constexpr int BM = 128, BK = 32, LDSS = BK + 4;       // 36 floats/row
    extern __shared__ float smf[];
    float* As = smf;                                       // [2][BM][36]
    float* Bs = smf + 2 * BM * LDSS;                       // [2][BN][36]

    if (batchH > 0) {
        int z = blockIdx.z;
        A  += (z / batchH) * aO + (z % batchH) * aI;
        Bp += (z / batchH) * bO + (z % batchH) * bI;
        C  += (z / batchH) * cO + (z % batchH) * cI;
    }
    int bx = blockIdx.x, by = blockIdx.y;
    if (flags & 16) { int t = bx; bx = by; by = t; }
    const int bm0 = by * BM;
    const int bn0 = bx * BN;
    if (flags & 4) { if (bn0 > bm0 + BM - 1) return; }
    int Keff = K;
    if (flags & 8) Keff = min(K, bm0 + BM);
    const int T = Keff / BK;

    const int tid  = threadIdx.x;
    const int w    = tid >> 5;
    const int lane = tid & 31;
    const int wm = w >> 2, wn = w & 3;
    const int g = lane >> 2, tig = lane & 3;
    constexpr int WN = BN / 4;
    constexpr int NT = WN / 8;            // n-tiles per warp (4 or 2)

    float acc[4][NT][4];
#pragma unroll
    for (int i = 0; i < 4; i++)
#pragma unroll
        for (int j = 0; j < NT; j++)
#pragma unroll
            for (int r = 0; r < 4; r++) acc[i][j][r] = 0.0f;

    const bool bK = (sBk == 1);

    // tile loaders -------------------------------------------------------
    auto load_tile = [&](int it, int buf) {
        const int k0 = it * BK;
        // A: 128x32, k-contiguous; 4 float4 per thread via cp.async
#pragma unroll
        for (int t = 0; t < 4; t++) {
            int vv = tid + t * 256;
            int m = vv >> 3, kq = vv & 7;
            cp16(smem_u32(&As[buf * BM * LDSS + m * LDSS + kq * 4]),
                 A + (long)(bm0 + m) * lda + k0 + kq * 4);
        }
        if (bK) {
#pragma unroll
            for (int t = 0; t < BN / 32; t++) {
                int vv = tid + t * 256;
                int n = vv >> 3, kq = vv & 7;
                cp16(smem_u32(&Bs[buf * BN * LDSS + n * LDSS + kq * 4]),
                     Bp + (long)(bn0 + n) * sBn + k0 + kq * 4);
            }
        } else {
            // n-contiguous source: element (n, kk) = Bp[(k0+kk)*sBk + bn0+n]
#pragma unroll
            for (int t = 0; t < BN / 32; t++) {
                int vv = tid + t * 256;
                int kk = vv / (BN / 4), nq = vv % (BN / 4);
                float4 f = *reinterpret_cast<const float4*>(
                    Bp + (long)(k0 + kk) * sBk + bn0 + nq * 4);
                float* bb = &Bs[buf * BN * LDSS + (nq * 4) * LDSS + kk];
                bb[0 * LDSS] = f.x;
                bb[1 * LDSS] = f.y;
                bb[2 * LDSS] = f.z;
                bb[3 * LDSS] = f.w;
            }
        }
    };

    load_tile(0, 0);
    CP_COMMIT();

    for (int it = 0; it < T; it++) {
        const int buf = it & 1;
        if (it + 1 < T) {
            load_tile(it + 1, buf ^ 1);
            CP_COMMIT();
            CP_WAIT1();
        } else {
            CP_WAIT0();
        }
        __syncthreads();

        const float* Ab = As + buf * BM * LDSS;
        const float* Bb = Bs + buf * BN * LDSS;

#pragma unroll
        for (int ks = 0; ks < 4; ks++) {
            uint32_t af[4][4];
#pragma unroll
            for (int i = 0; i < 4; i++) {
                const float* ap = Ab + (wm * 64 + i * 16) * LDSS + ks * 8;
                af[i][0] = f2tf(ap[g * LDSS + tig]);
                af[i][1] = f2tf(ap[(g + 8) * LDSS + tig]);
                af[i][2] = f2tf(ap[g * LDSS + tig + 4]);
                af[i][3] = f2tf(ap[(g + 8) * LDSS + tig + 4]);
            }
            uint32_t bf[NT][2];
#pragma unroll
            for (int j = 0; j < NT; j++) {
                const float* bp = Bb + (wn * WN + j * 8 + g) * LDSS + ks * 8;
                bf[j][0] = f2tf(bp[tig]);
                bf[j][1] = f2tf(bp[tig + 4]);
            }
#pragma unroll
            for (int i = 0; i < 4; i++)
#pragma unroll
                for (int j = 0; j < NT; j++)
                    mma_tf32(acc[i][j], af[i], bf[j]);
        }
        __syncthreads();
    }

    // epilogue -----------------------------------------------------------
#pragma unroll
    for (int i = 0; i < 4; i++) {
        int r0 = bm0 + wm * 64 + i * 16 + g;
#pragma unroll
        for (int j = 0; j < NT; j++) {
            int c = bn0 + wn * WN + j * 8 + tig * 2;
            float e00 = acc[i][j][0], e01 = acc[i][j][1];
            float e10 = acc[i][j][2], e11 = acc[i][j][3];
            if (bias) {
                float2 bb = *reinterpret_cast<const float2*>(bias + c);
                e00 += bb.x; e01 += bb.y; e10 += bb.x; e11 += bb.y;
            }
            if (flags & 1) {
                e00 = gelu_exact(e00); e01 = gelu_exact(e01);
                e10 = gelu_exact(e10); e11 = gelu_exact(e11);
            }
            if (res) {
                float2 ra = *reinterpret_cast<const float2*>(
                    res + (long)r0 * ldr + c);
                float2 rb = *reinterpret_cast<const float2*>(
                    res + (long)(r0 + 8) * ldr + c);
                e00 += ra.x; e01 += ra.y; e10 += rb.x; e11 += rb.y;
            }
            *reinterpret_cast<float2*>(C + (long)r0 * ldc + c) =
                make_float2(e00, e01);
            *reinterpret_cast<float2*>(C + (long)(r0 + 8) * ldc + c) =
                make_float2(e10, e11);
        }
    }
}

// ---------------- host-side launch helpers ----------------
static constexpr int SMEM128 = (2 * 128 * 36 + 2 * 128 * 36) * 4;  // 73728
static constexpr int SMEM64  = (2 * 128 * 36 + 2 * 64  * 36) * 4;  // 55296

static void tgemm128(const float* A, int lda, const float* B, long sBn, long sBk,
                     const float* bias, const float* res, int ldr,
                     float* C, int ldc, int M, int N, int K, int flags,
                     int batch = 1, int batchH = 0,
                     long aO = 0, long aI = 0, long bO = 0, long bI = 0,
                     long cO = 0, long cI = 0) {
    dim3 gdim;
    if (flags & 16) gdim = dim3(M / 128, N / 128, batch);
    else            gdim = dim3(N / 128, M / 128, batch);
    mma_gemm<128><<<gdim, 256, SMEM128>>>(A, lda, B, sBn, sBk, bias, res, ldr,
                                          C, ldc, K, flags, batchH,
                                          aO, aI, bO, bI, cO, cI);
}
static void tgemm64(const float* A, int lda, const float* B, long sBn, long sBk,
                    const float* bias, const float* res, int ldr,
                    float* C, int ldc, int M, int N, int K, int flags,
                    int batch = 1, int batchH = 0,
                    long aO = 0, long aI = 0, long bO = 0, long bI = 0,
                    long cO = 0, long cI = 0) {
    dim3 gdim(N / 64, M / 128, batch);
    mma_gemm<64><<<gdim, 256, SMEM64>>>(A, lda, B, sBn, sBk, bias, res, ldr,
                                        C, ldc, K, flags, batchH,
                                        aO, aI, bO, bI, cO, cI);
}

// ---------------- entry point ----------------
extern "C" void kernel_launch(void* const* d_in, const int* in_sizes, int n_in,
                              void* d_out, int out_size) {
    // dict order: 0 idx, 1 tok, 2 pos, 3 phase, 4 ln1_w, 5 ln1_b, 6 ln2_w, 7 ln2_b,
    // 8..23 {W,b,B,A} x {q,k,v,o}, 24 W1, 25 b1, 26 W2, 27 b2, 28 lnf_w, 29 lnf_b, 30 head_W
    const int*   idx   = (const int*)  d_in[0];
    const float* tok   = (const float*)d_in[1];
    const float* pos   = (const float*)d_in[2];
    const float* phase = (const float*)d_in[3];
    const float* ln1w  = (const float*)d_in[4];
    const float* ln1b  = (const float*)d_in[5];

    const float *ln2w, *ln2b;
    int wbase;
    if (in_sizes[6] == DEPTH * DMODEL) {        // dict order
        ln2w = (const float*)d_in[6];
        ln2b = (const float*)d_in[7];
        wbase = 8;
    } else {                                     // signature order fallback
        ln2w = (const float*)d_in[22];
        ln2b = (const float*)d_in[23];
        wbase = 6;
    }
    const float* Wq = (const float*)d_in[wbase + 0];
    const float* bq = (const float*)d_in[wbase + 1];
    const float* Bq = (const float*)d_in[wbase + 2];
    const float* Aq = (const float*)d_in[wbase + 3];
    const float* Wk = (const float*)d_in[wbase + 4];
    const float* bk = (const float*)d_in[wbase + 5];
    const float* Bk = (const float*)d_in[wbase + 6];
    const float* Ak = (const float*)d_in[wbase + 7];
    const float* Wv = (const float*)d_in[wbase + 8];
    const float* bv = (const float*)d_in[wbase + 9];
    const float* Bv = (const float*)d_in[wbase + 10];
    const float* Av = (const float*)d_in[wbase + 11];
    const float* Wo = (const float*)d_in[wbase + 12];
    const float* bo = (const float*)d_in[wbase + 13];
    const float* Bo = (const float*)d_in[wbase + 14];
    const float* Ao = (const float*)d_in[wbase + 15];
    const float* W1 = (const float*)d_in[24];
    const float* b1 = (const float*)d_in[25];
    const float* W2 = (const float*)d_in[26];
    const float* b2 = (const float*)d_in[27];
    const float* lnfw = (const float*)d_in[28];
    const float* lnfb = (const float*)d_in[29];
    const float* headW = (const float*)d_in[30];
    float* out = (float*)d_out;

    float *x, *h, *qkv, *o, *ff, *sc, *wqkv, *bqkv, *wo;
    cudaGetSymbolAddress((void**)&x,   g_x);
    cudaGetSymbolAddress((void**)&h,   g_h);
    cudaGetSymbolAddress((void**)&qkv, g_qkv);
    cudaGetSymbolAddress((void**)&o,   g_o);
    cudaGetSymbolAddress((void**)&ff,  g_ff);
    cudaGetSymbolAddress((void**)&sc,  g_scores);
    cudaGetSymbolAddress((void**)&wqkv, g_wqkv);
    cudaGetSymbolAddress((void**)&bqkv, g_bqkv);
    cudaGetSymbolAddress((void**)&wo,  g_wo);

    cudaFuncSetAttribute(mma_gemm<128>,
                         cudaFuncAttributeMaxDynamicSharedMemorySize, SMEM128);
    cudaFuncSetAttribute(mma_gemm<64>,
                         cudaFuncAttributeMaxDynamicSharedMemorySize, SMEM64);

    const int D = DMODEL, L = SEQL, Hh = NHEAD, HD = HEADDIM;
    const long DD = (long)D * D;
    const long LL = (long)L * L;
    const long LD3 = (long)L * 3 * D;

    // 1) fold LoRA into effective weights (QKV concatenated)
    {
        int nblk = (int)(DEPTH * DD / 4 / 256);
        weff_kernel<<<nblk, 256>>>(Wq, Aq, Bq, wqkv, 3 * DD, 0);
        weff_kernel<<<nblk, 256>>>(Wk, Ak, Bk, wqkv, 3 * DD, DD);
        weff_kernel<<<nblk, 256>>>(Wv, Av, Bv, wqkv, 3 * DD, 2 * DD);
        weff_kernel<<<nblk, 256>>>(Wo, Ao, Bo, wo, DD, 0);
        bias_concat_kernel<<<DEPTH * 3 * D / 256, 256>>>(bq, bk, bv, bqkv);
    }

    // 2) embedding + phase rotator
    embed_kernel<<<NTOK, 256>>>(idx, tok, pos, phase, x);

    // 3) transformer layers
    for (int i = 0; i < DEPTH; i++) {
        const float* wqkv_i = wqkv + (long)i * 3 * DD;
        const float* woi    = wo + (long)i * DD;

        ln_kernel<<<NTOK, 256>>>(x, ln1w + i * D, ln1b + i * D, h);

        // fused QKV: qkv[NTOK, 3072]
        tgemm128(h, D, wqkv_i, D, 1, bqkv + (long)i * 3 * D, nullptr, 0,
                 qkv, 3 * D, NTOK, 3 * D, D, 0);

        // scores[z][l][j] = q . k  (batched over B*H, causal tile-skip)
        tgemm128(qkv, 3 * D, qkv + D, 3 * D, 1, nullptr, nullptr, 0, sc, L,
                 L, L, HD, /*flags=*/4,
                 BATCH * Hh, Hh,
                 LD3, HD, LD3, HD,
                 (long)Hh * LL, LL);

        softmax_kernel<<<BATCH * Hh * L, 256>>>(sc);

        // o = attn @ V (batched, causal K-limit); B elem (n,k') = v[k'*3D + n]
        tgemm64(sc, L, qkv + 2 * D, 1, 3 * D, nullptr, nullptr, 0, o, D,
                L, HD, L, /*flags=*/8,
                BATCH * Hh, Hh,
                (long)Hh * LL, LL,
                LD3, HD,
                (long)L * D, HD);

        // x = x + o @ Wo_eff^T + bo
        tgemm128(o, D, woi, D, 1, bo + i * D, x, D, x, D, NTOK, D, D, 0);

        ln_kernel<<<NTOK, 256>>>(x, ln2w + i * D, ln2b + i * D, h);

        // ff = gelu(h @ W1^T + b1)
        tgemm128(h, D, W1 + (long)i * HIDDEN * D, D, 1, b1 + i * HIDDEN,
                 nullptr, 0, ff, HIDDEN, NTOK, HIDDEN, D, /*flags=*/1);
        // x = x + ff @ W2^T + b2
        tgemm128(ff, HIDDEN, W2 + (long)i * D * HIDDEN, HIDDEN, 1, b2 + i * D,
                 x, D, x, D, NTOK, D, HIDDEN, 0);
    }

    // 4) final LN + LM head (grid-swapped: M-blocks vary fastest for L2 B reuse)
    ln_kernel<<<NTOK, 256>>>(x, lnfw, lnfb, h);
    tgemm128(h, D, headW, D, 1, nullptr, nullptr, 0, out, VOCAB,
             NTOK, VOCAB, D, /*flags=*/16);
}

// round 7
// speedup vs baseline: 1.2838x; 1.1133x over previous
#include <cuda_runtime.h>
#include <cuda_bf16.h>
#include <cstdint>
#include <math.h>

// ---------------- Problem constants ----------------
#define VOCAB 32000
#define DMODEL 1024
#define DEPTH 6
#define NHEAD 16
#define SEQL 1024
#define BATCH 2
#define LRANK 16
#define HIDDEN 4096
#define HEADDIM 64
#define NTOK (BATCH * SEQL)          // 2048
#define SCALING 0.5f                  // 8.0 / 16

// ---------------- Scratch (device globals; no allocation allowed) -------------
static __device__ float g_x  [NTOK * DMODEL];
static __device__ float g_h  [NTOK * DMODEL];
static __device__ float g_qkv[NTOK * 3 * DMODEL];
static __device__ float g_o  [NTOK * DMODEL];
static __device__ float g_ff [NTOK * HIDDEN];
static __device__ float g_wqkv[DEPTH * 3 * DMODEL * DMODEL];
static __device__ float g_bqkv[DEPTH * 3 * DMODEL];
static __device__ float g_wo  [DEPTH * DMODEL * DMODEL];

// ---------------- small PTX helpers (baseline ISA only) ----------------
__device__ __forceinline__ uint32_t smem_u32(const void* p) {
    uint32_t a;
    asm("{ .reg .u64 t; cvta.to.shared.u64 t, %1; cvt.u32.u64 %0, t; }"
        : "=r"(a) : "l"(p));
    return a;
}
__device__ __forceinline__ void cp16(uint32_t dst, const void* src) {
    asm volatile("cp.async.cg.shared.global [%0], [%1], 16;"
                 :: "r"(dst), "l"(src));
}
#define CP_COMMIT() asm volatile("cp.async.commit_group;" ::: "memory")
#define CP_WAIT1()  asm volatile("cp.async.wait_group 1;"  ::: "memory")
#define CP_WAIT0()  asm volatile("cp.async.wait_group 0;"  ::: "memory")

__device__ __forceinline__ uint32_t f2tf(float f) {
    uint32_t u;
    asm("cvt.rna.tf32.f32 %0, %1;" : "=r"(u) : "f"(f));
    return u;
}
__device__ __forceinline__ void mma_tf32(float* d, const uint32_t* a,
                                         const uint32_t* b) {
    asm volatile(
        "mma.sync.aligned.m16n8k8.row.col.f32.tf32.tf32.f32 "
        "{%0,%1,%2,%3}, {%4,%5,%6,%7}, {%8,%9}, {%0,%1,%2,%3};"
        : "+f"(d[0]), "+f"(d[1]), "+f"(d[2]), "+f"(d[3])
        : "r"(a[0]), "r"(a[1]), "r"(a[2]), "r"(a[3]), "r"(b[0]), "r"(b[1]));
}

// ---------------- helpers ----------------
__device__ __forceinline__ float gelu_exact(float x) {
    return 0.5f * x * (1.0f + erff(x * 0.70710678118654752440f));
}

// ---------------- LoRA fold body ----------------
__device__ __forceinline__ void weff_body(long e4,
                                          const float* __restrict__ W,
                                          const float* __restrict__ Am,
                                          const float* __restrict__ Bm,
                                          float* __restrict__ out,
                                          long outLS, long outOff) {
    const int DD4 = DMODEL * DMODEL / 4;
    int layer = (int)(e4 / DD4);
    int rem4  = (int)(e4 % DD4);
    int orow  = rem4 / (DMODEL / 4);
    int ic4   = (rem4 % (DMODEL / 4)) * 4;
    const float* a  = Am + (long)layer * DMODEL * LRANK + (long)orow * LRANK;
    const float* bb = Bm + (long)layer * LRANK * DMODEL + ic4;
    float4 s = make_float4(0.f, 0.f, 0.f, 0.f);
#pragma unroll
    for (int r = 0; r < LRANK; r++) {
        float4 bv = *reinterpret_cast<const float4*>(bb + (long)r * DMODEL);
        float av = a[r];
        s.x += av * bv.x; s.y += av * bv.y; s.z += av * bv.z; s.w += av * bv.w;
    }
    float4 wv = *reinterpret_cast<const float4*>(
        W + (long)layer * DMODEL * DMODEL + rem4 * 4);
    wv.x += SCALING * s.x; wv.y += SCALING * s.y;
    wv.z += SCALING * s.z; wv.w += SCALING * s.w;
    *reinterpret_cast<float4*>(
        out + (long)layer * outLS + outOff + rem4 * 4) = wv;
}

// fused q/k/v LoRA fold: one kernel, 3 segments
__global__ void weff_qkv_kernel(const float* __restrict__ Wq, const float* __restrict__ Aq, const float* __restrict__ Bq,
                                const float* __restrict__ Wk, const float* __restrict__ Ak, const float* __restrict__ Bk,
                                const float* __restrict__ Wv, const float* __restrict__ Av, const float* __restrict__ Bv,
                                float* __restrict__ out) {
    const int nblk = DEPTH * DMODEL * DMODEL / 4 / 256;
    int seg = blockIdx.x / nblk;
    long e4 = (long)(blockIdx.x % nblk) * 256 + threadIdx.x;
    const long DD = (long)DMODEL * DMODEL;
    const float *W = (seg == 0) ? Wq : (seg == 1 ? Wk : Wv);
    const float *A = (seg == 0) ? Aq : (seg == 1 ? Ak : Av);
    const float *B = (seg == 0) ? Bq : (seg == 1 ? Bk : Bv);
    weff_body(e4, W, A, B, out, 3 * DD, seg * DD);
}

__global__ void weff_kernel(const float* __restrict__ W,
                            const float* __restrict__ Am,
                            const float* __restrict__ Bm,
                            float* __restrict__ out,
                            long outLS, long outOff) {
    long e4 = (long)blockIdx.x * 256 + threadIdx.x;
    weff_body(e4, W, Am, Bm, out, outLS, outOff);
}

// ---------------- bias concat for fused QKV ----------------
__global__ void bias_concat_kernel(const float* __restrict__ bq,
                                   const float* __restrict__ bk,
                                   const float* __restrict__ bv,
                                   float* __restrict__ out) {
    int e = blockIdx.x * 256 + threadIdx.x;       // DEPTH * 3 * D
    int layer = e / (3 * DMODEL);
    int r = e % (3 * DMODEL);
    const float* src = (r < DMODEL) ? bq : (r < 2 * DMODEL ? bk : bv);
    out[e] = src[layer * DMODEL + (r % DMODEL)];
}

// ---------------- Embedding + phase rotator ----------------
__global__ void embed_kernel(const int* __restrict__ idx,
                             const float* __restrict__ tok,
                             const float* __restrict__ pos,
                             const float* __restrict__ phase,
                             float* __restrict__ x) {
    int row = blockIdx.x;
    int l   = row % SEQL;
    int t   = idx[row];
    for (int d = threadIdx.x; d < DMODEL; d += blockDim.x) {
        float phi = tanhf(phase[d]) * 3.14159265358979323846f;
        float fac = cosf(phi) - sinf(phi);
        x[(long)row * DMODEL + d] =
            (tok[(long)t * DMODEL + d] + pos[(long)l * DMODEL + d]) * fac;
    }
}

// ---------------- LayerNorm ----------------
__global__ void ln_kernel(const float* __restrict__ x,
                          const float* __restrict__ w,
                          const float* __restrict__ b,
                          float* __restrict__ o) {
    int row = blockIdx.x;
    const float* xr = x + (long)row * DMODEL;
    int tid = threadIdx.x;
    float s = 0.f, s2 = 0.f;
    float v[4];
#pragma unroll
    for (int j = 0; j < 4; j++) {
        v[j] = xr[tid + 256 * j];
        s += v[j]; s2 += v[j] * v[j];
    }
    __shared__ float r1[256], r2[256];
    r1[tid] = s; r2[tid] = s2;
    __syncthreads();
    for (int off = 128; off > 0; off >>= 1) {
        if (tid < off) { r1[tid] += r1[tid + off]; r2[tid] += r2[tid + off]; }
        __syncthreads();
    }
    float mean = r1[0] * (1.0f / DMODEL);
    float var  = r2[0] * (1.0f / DMODEL) - mean * mean;
    float rstd = rsqrtf(var + 1e-5f);
    float* orow = o + (long)row * DMODEL;
#pragma unroll
    for (int j = 0; j < 4; j++) {
        int d = tid + 256 * j;
        orow[d] = (v[j] - mean) * rstd * w[d] + b[d];
    }
}

// ---------------- Fused flash attention (tf32 MMA, online softmax) ----------
// grid: (8 q-tiles, 32 batch-heads), 256 threads (8 warps x 16 q-rows).
// qkv: [NTOK][3*DMODEL]; o: [NTOK][DMODEL].
// SMEM: Kt[128][68] f32->tf32 | Vraw[128][68] | VtT[64][132] u32 | Pu[128][134] u32
static constexpr int FA_K_OFF   = 0;
static constexpr int FA_V_OFF   = 128 * 68;
static constexpr int FA_VT_OFF  = 2 * 128 * 68;
static constexpr int FA_P_OFF   = 2 * 128 * 68 + 64 * 132;
static constexpr int FA_WORDS   = FA_P_OFF + 128 * 134;          // 43008
static constexpr int FA_SMEM    = FA_WORDS * 4;                   // 172032 B

__global__ __launch_bounds__(256)
void flash_attn_kernel(const float* __restrict__ qkv, float* __restrict__ o) {
    extern __shared__ float fs[];
    float*    Kt   = fs + FA_K_OFF;
    float*    Vraw = fs + FA_V_OFF;
    uint32_t* VtT  = (uint32_t*)(fs + FA_VT_OFF);
    uint32_t* Pu   = (uint32_t*)(fs + FA_P_OFF);
    float*    Qs   = (float*)Pu;                 // Q staging reuses P region

    const int qt = blockIdx.x;        // 0..7
    const int bh = blockIdx.y;        // 0..31
    const int b  = bh >> 4;
    const int h  = bh & 15;

    const int tid  = threadIdx.x;
    const int wid  = tid >> 5;
    const int lane = tid & 31;
    const int g = lane >> 2, tig = lane & 3;

    const float* base = qkv + ((long)b * SEQL) * (3 * DMODEL) + h * HEADDIM;

    // ---- stage Q tile, build A-fragments in registers (scaled by 1/8 exactly)
    {
        int r = tid >> 1, half = tid & 1;
        const float* src = base + (long)(qt * 128 + r) * (3 * DMODEL) + half * 32;
        uint32_t dst = smem_u32(&Qs[r * 68 + half * 32]);
#pragma unroll
        for (int i = 0; i < 8; i++) cp16(dst + i * 16, src + i * 4);
    }
    CP_COMMIT(); CP_WAIT0(); __syncthreads();

    uint32_t qf[8][4];
    {
        const float* qp = Qs + (wid * 16) * 68;
#pragma unroll
        for (int ks = 0; ks < 8; ks++) {
            qf[ks][0] = f2tf(0.125f * qp[(g    ) * 68 + ks * 8 + tig]);
            qf[ks][1] = f2tf(0.125f * qp[(g + 8) * 68 + ks * 8 + tig]);
            qf[ks][2] = f2tf(0.125f * qp[(g    ) * 68 + ks * 8 + tig + 4]);
            qf[ks][3] = f2tf(0.125f * qp[(g + 8) * 68 + ks * 8 + tig + 4]);
        }
    }
    __syncthreads();                  // Q consumed before P region reuse

    float mold0 = -INFINITY, mold1 = -INFINITY;
    float l0 = 0.f, l1 = 0.f;
    float oacc[8][4];
#pragma unroll
    for (int n = 0; n < 8; n++)
#pragma unroll
        for (int r = 0; r < 4; r++) oacc[n][r] = 0.f;

    for (int kt = 0; kt <= qt; kt++) {
        // ---- load K,V tiles (raw fp32)
        {
            int r = tid >> 1, half = tid & 1;
            const float* ksrc = base + (long)(kt * 128 + r) * (3 * DMODEL) + DMODEL + half * 32;
            const float* vsrc = base + (long)(kt * 128 + r) * (3 * DMODEL) + 2 * DMODEL + half * 32;
            uint32_t kd = smem_u32(&Kt[r * 68 + half * 32]);
            uint32_t vd = smem_u32(&Vraw[r * 68 + half * 32]);
#pragma unroll
            for (int i = 0; i < 8; i++) cp16(kd + i * 16, ksrc + i * 4);
#pragma unroll
            for (int i = 0; i < 8; i++) cp16(vd + i * 16, vsrc + i * 4);
        }
        CP_COMMIT(); CP_WAIT0(); __syncthreads();

        // ---- convert K in place to tf32; build transposed tf32 V
        {
            int r = tid >> 1, half = tid & 1;
            uint4* krow = (uint4*)&Kt[r * 68 + half * 32];
#pragma unroll
            for (int i = 0; i < 8; i++) {
                uint4 u = krow[i];
                u.x = f2tf(__uint_as_float(u.x));
                u.y = f2tf(__uint_as_float(u.y));
                u.z = f2tf(__uint_as_float(u.z));
                u.w = f2tf(__uint_as_float(u.w));
                krow[i] = u;
            }
            const float4* vrow = (const float4*)&Vraw[r * 68 + half * 32];
#pragma unroll
            for (int i = 0; i < 8; i++) {
                float4 f = vrow[i];
                int c = half * 32 + i * 4;
                VtT[(c + 0) * 132 + r] = f2tf(f.x);
                VtT[(c + 1) * 132 + r] = f2tf(f.y);
                VtT[(c + 2) * 132 + r] = f2tf(f.z);
                VtT[(c + 3) * 132 + r] = f2tf(f.w);
            }
        }
        __syncthreads();

        // ---- S = Q @ K^T  (warp covers its 16 rows x all 128 keys)
        float sacc[16][4];
#pragma unroll
        for (int n = 0; n < 16; n++)
#pragma unroll
            for (int r = 0; r < 4; r++) sacc[n][r] = 0.f;
        const uint32_t* Ku = (const uint32_t*)Kt;
#pragma unroll
        for (int nt = 0; nt < 16; nt++) {
            const uint32_t* kp = Ku + (nt * 8 + g) * 68;
#pragma unroll
            for (int ks = 0; ks < 8; ks++) {
                uint32_t bf[2];
                bf[0] = kp[ks * 8 + tig];
                bf[1] = kp[ks * 8 + tig + 4];
                mma_tf32(sacc[nt], qf[ks], bf);
            }
        }

        // ---- causal mask on diagonal tile
        if (kt == qt) {
            int r0 = wid * 16 + g, r1 = r0 + 8;
#pragma unroll
            for (int nt = 0; nt < 16; nt++) {
                int c0 = nt * 8 + tig * 2;
                if (c0     > r0) sacc[nt][0] = -INFINITY;
                if (c0 + 1 > r0) sacc[nt][1] = -INFINITY;
                if (c0     > r1) sacc[nt][2] = -INFINITY;
                if (c0 + 1 > r1) sacc[nt][3] = -INFINITY;
            }
        }

        // ---- online softmax (rows g / g+8 within warp block)
        float tm0 = -INFINITY, tm1 = -INFINITY;
#pragma unroll
        for (int nt = 0; nt < 16; nt++) {
            tm0 = fmaxf(tm0, fmaxf(sacc[nt][0], sacc[nt][1]));
            tm1 = fmaxf(tm1, fmaxf(sacc[nt][2], sacc[nt][3]));
        }
        tm0 = fmaxf(tm0, __shfl_xor_sync(0xffffffffu, tm0, 1));
        tm0 = fmaxf(tm0, __shfl_xor_sync(0xffffffffu, tm0, 2));
        tm1 = fmaxf(tm1, __shfl_xor_sync(0xffffffffu, tm1, 1));
        tm1 = fmaxf(tm1, __shfl_xor_sync(0xffffffffu, tm1, 2));
        float mn0 = fmaxf(mold0, tm0), mn1 = fmaxf(mold1, tm1);
        float a0 = __expf(mold0 - mn0), a1 = __expf(mold1 - mn1);

        float sum0 = 0.f, sum1 = 0.f;
        int prow = wid * 16 + g;
#pragma unroll
        for (int nt = 0; nt < 16; nt++) {
            float p0 = __expf(sacc[nt][0] - mn0);
            float p1 = __expf(sacc[nt][1] - mn0);
            float p2 = __expf(sacc[nt][2] - mn1);
            float p3 = __expf(sacc[nt][3] - mn1);
            sum0 += p0 + p1; sum1 += p2 + p3;
            int c = nt * 8 + tig * 2;
            uint2 u01 = make_uint2(f2tf(p0), f2tf(p1));
            uint2 u23 = make_uint2(f2tf(p2), f2tf(p3));
            *(uint2*)&Pu[(prow    ) * 134 + c] = u01;
            *(uint2*)&Pu[(prow + 8) * 134 + c] = u23;
        }
        sum0 += __shfl_xor_sync(0xffffffffu, sum0, 1);
        sum0 += __shfl_xor_sync(0xffffffffu, sum0, 2);
        sum1 += __shfl_xor_sync(0xffffffffu, sum1, 1);
        sum1 += __shfl_xor_sync(0xffffffffu, sum1, 2);
        l0 = l0 * a0 + sum0;
        l1 = l1 * a1 + sum1;
#pragma unroll
        for (int nt = 0; nt < 8; nt++) {
            oacc[nt][0] *= a0; oacc[nt][1] *= a0;
            oacc[nt][2] *= a1; oacc[nt][3] *= a1;
        }
        mold0 = mn0; mold1 = mn1;
        __syncthreads();

        // ---- O += P @ V
#pragma unroll
        for (int ks = 0; ks < 16; ks++) {
            uint32_t af[4];
            const uint32_t* pp = Pu + (wid * 16) * 134 + ks * 8;
            af[0] = pp[(g    ) * 134 + tig];
            af[1] = pp[(g + 8) * 134 + tig];
            af[2] = pp[(g    ) * 134 + tig + 4];
            af[3] = pp[(g + 8) * 134 + tig + 4];
#pragma unroll
            for (int nt = 0; nt < 8; nt++) {
                uint32_t bf[2];
                bf[0] = VtT[(nt * 8 + g) * 132 + ks * 8 + tig];
                bf[1] = VtT[(nt * 8 + g) * 132 + ks * 8 + tig + 4];
                mma_tf32(oacc[nt], af, bf);
            }
        }
        __syncthreads();      // K/V/P reused next iteration
    }

    // ---- normalize and write O
    float i0 = 1.0f / l0, i1 = 1.0f / l1;
    int tok = b * SEQL + qt * 128 + wid * 16 + g;
    float* o0 = o + (long)tok * DMODEL + h * HEADDIM;
    float* o1 = o0 + 8 * DMODEL;
#pragma unroll
    for (int nt = 0; nt < 8; nt++) {
        int c = nt * 8 + tig * 2;
        *(float2*)&o0[c] = make_float2(oacc[nt][0] * i0, oacc[nt][1] * i0);
        *(float2*)&o1[c] = make_float2(oacc[nt][2] * i1, oacc[nt][3] * i1);
    }
}

// ---------------- tf32 mma.sync GEMM (R6 core, unchanged) ----------------
// flags: 1 = gelu, 4 = causal tile-skip, 8 = causal K-limit, 16 = grid swap
template<int BN>
__global__ __launch_bounds__(256)
void mma_gemm(const float* __restrict__ A, int lda,
              const float* __restrict__ Bp, long sBn, long sBk,
              const float* __restrict__ bias,
              const float* __restrict__ res, int ldr,
              float* __restrict__ C, int ldc,
              int K, int flags, int batchH,
              long aO, long aI, long bO, long bI, long cO, long cI) {
    constexpr int BM = 128, BK = 32, LDSS = BK + 4;
    extern __shared__ float smf[];
    float* As = smf;
    float* Bs = smf + 2 * BM * LDSS;

    if (batchH > 0) {
        int z = blockIdx.z;
        A  += (z / batchH) * aO + (z % batchH) * aI;
        Bp += (z / batchH) * bO + (z % batchH) * bI;
        C  += (z / batchH) * cO + (z % batchH) * cI;
    }
    int bx = blockIdx.x, by = blockIdx.y;
    if (flags & 16) { int t = bx; bx = by; by = t; }
    const int bm0 = by * BM;
    const int bn0 = bx * BN;
    if (flags & 4) { if (bn0 > bm0 + BM - 1) return; }
    int Keff = K;
    if (flags & 8) Keff = min(K, bm0 + BM);
    const int T = Keff / BK;

    const int tid  = threadIdx.x;
    const int w    = tid >> 5;
    const int lane = tid & 31;
    const int wm = w >> 2, wn = w & 3;
    const int g = lane >> 2, tig = lane & 3;
    constexpr int WN = BN / 4;
    constexpr int NT = WN / 8;

    float acc[4][NT][4];
#pragma unroll
    for (int i = 0; i < 4; i++)
#pragma unroll
        for (int j = 0; j < NT; j++)
#pragma unroll
            for (int r = 0; r < 4; r++) acc[i][j][r] = 0.0f;

    const bool bK = (sBk == 1);

    auto load_tile = [&](int it, int buf) {
        const int k0 = it * BK;
#pragma unroll
        for (int t = 0; t < 4; t++) {
            int vv = tid + t * 256;
            int m = vv >> 3, kq = vv & 7;
            cp16(smem_u32(&As[buf * BM * LDSS + m * LDSS + kq * 4]),
                 A + (long)(bm0 + m) * lda + k0 + kq * 4);
        }
        if (bK) {
#pragma unroll
            for (int t = 0; t < BN / 32; t++) {
                int vv = tid + t * 256;
                int n = vv >> 3, kq = vv & 7;
                cp16(smem_u32(&Bs[buf * BN * LDSS + n * LDSS + kq * 4]),
                     Bp + (long)(bn0 + n) * sBn + k0 + kq * 4);
            }
        } else {
#pragma unroll
            for (int t = 0; t < BN / 32; t++) {
                int vv = tid + t * 256;
                int kk = vv / (BN / 4), nq = vv % (BN / 4);
                float4 f = *reinterpret_cast<const float4*>(
                    Bp + (long)(k0 + kk) * sBk + bn0 + nq * 4);
                float* bb = &Bs[buf * BN * LDSS + (nq * 4) * LDSS + kk];
                bb[0 * LDSS] = f.x;
                bb[1 * LDSS] = f.y;
                bb[2 * LDSS] = f.z;
                bb[3 * LDSS] = f.w;
            }
        }
    };

    load_tile(0, 0);
    CP_COMMIT();

    for (int it = 0; it < T; it++) {
        const int buf = it & 1;
        if (it + 1 < T) {
            load_tile(it + 1, buf ^ 1);
            CP_COMMIT();
            CP_WAIT1();
        } else {
            CP_WAIT0();
        }
        __syncthreads();

        const float* Ab = As + buf * BM * LDSS;
        const float* Bb = Bs + buf * BN * LDSS;

#pragma unroll
        for (int ks = 0; ks < 4; ks++) {
            uint32_t af[4][4];
#pragma unroll
            for (int i = 0; i < 4; i++) {
                const float* ap = Ab + (wm * 64 + i * 16) * LDSS + ks * 8;
                af[i][0] = f2tf(ap[g * LDSS + tig]);
                af[i][1] = f2tf(ap[(g + 8) * LDSS + tig]);
                af[i][2] = f2tf(ap[g * LDSS + tig + 4]);
                af[i][3] = f2tf(ap[(g + 8) * LDSS + tig + 4]);
            }
            uint32_t bf[NT][2];
#pragma unroll
            for (int j = 0; j < NT; j++) {
                const float* bp = Bb + (wn * WN + j * 8 + g) * LDSS + ks * 8;
                bf[j][0] = f2tf(bp[tig]);
                bf[j][1] = f2tf(bp[tig + 4]);
            }
#pragma unroll
            for (int i = 0; i < 4; i++)
#pragma unroll
                for (int j = 0; j < NT; j++)
                    mma_tf32(acc[i][j], af[i], bf[j]);
        }
        __syncthreads();
    }

#pragma unroll
    for (int i = 0; i < 4; i++) {
        int r0 = bm0 + wm * 64 + i * 16 + g;
#pragma unroll
        for (int j = 0; j < NT; j++) {
            int c = bn0 + wn * WN + j * 8 + tig * 2;
            float e00 = acc[i][j][0], e01 = acc[i][j][1];
            float e10 = acc[i][j][2], e11 = acc[i][j][3];
            if (bias) {
                float2 bb = *reinterpret_cast<const float2*>(bias + c);
                e00 += bb.x; e01 += bb.y; e10 += bb.x; e11 += bb.y;
            }
            if (flags & 1) {
                e00 = gelu_exact(e00); e01 = gelu_exact(e01);
                e10 = gelu_exact(e10); e11 = gelu_exact(e11);
            }
            if (res) {
                float2 ra = *reinterpret_cast<const float2*>(
                    res + (long)r0 * ldr + c);
                float2 rb = *reinterpret_cast<const float2*>(
                    res + (long)(r0 + 8) * ldr + c);
                e00 += ra.x; e01 += ra.y; e10 += rb.x; e11 += rb.y;
            }
            *reinterpret_cast<float2*>(C + (long)r0 * ldc + c) =
                make_float2(e00, e01);
            *reinterpret_cast<float2*>(C + (long)(r0 + 8) * ldc + c) =
                make_float2(e10, e11);
        }
    }
}

// ---------------- host-side launch helpers ----------------
static constexpr int SMEM128 = (2 * 128 * 36 + 2 * 128 * 36) * 4;  // 73728

static void tgemm128(const float* A, int lda, const float* B, long sBn, long sBk,
                     const float* bias, const float* res, int ldr,
                     float* C, int ldc, int M, int N, int K, int flags) {
    dim3 gdim;
    if (flags & 16) gdim = dim3(M / 128, N / 128, 1);
    else            gdim = dim3(N / 128, M / 128, 1);
    mma_gemm<128><<<gdim, 256, SMEM128>>>(A, lda, B, sBn, sBk, bias, res, ldr,
                                          C, ldc, K, flags, 0,
                                          0, 0, 0, 0, 0, 0);
}

// ---------------- entry point ----------------
extern "C" void kernel_launch(void* const* d_in, const int* in_sizes, int n_in,
                              void* d_out, int out_size) {
    // dict order: 0 idx, 1 tok, 2 pos, 3 phase, 4 ln1_w, 5 ln1_b, 6 ln2_w, 7 ln2_b,
    // 8..23 {W,b,B,A} x {q,k,v,o}, 24 W1, 25 b1, 26 W2, 27 b2, 28 lnf_w, 29 lnf_b, 30 head_W
    const int*   idx   = (const int*)  d_in[0];
    const float* tok   = (const float*)d_in[1];
    const float* pos   = (const float*)d_in[2];
    const float* phase = (const float*)d_in[3];
    const float* ln1w  = (const float*)d_in[4];
    const float* ln1b  = (const float*)d_in[5];

    const float *ln2w, *ln2b;
    int wbase;
    if (in_sizes[6] == DEPTH * DMODEL) {        // dict order
        ln2w = (const float*)d_in[6];
        ln2b = (const float*)d_in[7];
        wbase = 8;
    } else {                                     // signature order fallback
        ln2w = (const float*)d_in[22];
        ln2b = (const float*)d_in[23];
        wbase = 6;
    }
    const float* Wq = (const float*)d_in[wbase + 0];
    const float* bq = (const float*)d_in[wbase + 1];
    const float* Bq = (const float*)d_in[wbase + 2];
    const float* Aq = (const float*)d_in[wbase + 3];
    const float* Wk = (const float*)d_in[wbase + 4];
    const float* bk = (const float*)d_in[wbase + 5];
    const float* Bk = (const float*)d_in[wbase + 6];
    const float* Ak = (const float*)d_in[wbase + 7];
    const float* Wv = (const float*)d_in[wbase + 8];
    const float* bv = (const float*)d_in[wbase + 9];
    const float* Bv = (const float*)d_in[wbase + 10];
    const float* Av = (const float*)d_in[wbase + 11];
    const float* Wo = (const float*)d_in[wbase + 12];
    const float* bo = (const float*)d_in[wbase + 13];
    const float* Bo = (const float*)d_in[wbase + 14];
    const float* Ao = (const float*)d_in[wbase + 15];
    const float* W1 = (const float*)d_in[24];
    const float* b1 = (const float*)d_in[25];
    const float* W2 = (const float*)d_in[26];
    const float* b2 = (const float*)d_in[27];
    const float* lnfw = (const float*)d_in[28];
    const float* lnfb = (const float*)d_in[29];
    const float* headW = (const float*)d_in[30];
    float* out = (float*)d_out;

    float *x, *h, *qkv, *o, *ff, *wqkv, *bqkv, *wo;
    cudaGetSymbolAddress((void**)&x,   g_x);
    cudaGetSymbolAddress((void**)&h,   g_h);
    cudaGetSymbolAddress((void**)&qkv, g_qkv);
    cudaGetSymbolAddress((void**)&o,   g_o);
    cudaGetSymbolAddress((void**)&ff,  g_ff);
    cudaGetSymbolAddress((void**)&wqkv, g_wqkv);
    cudaGetSymbolAddress((void**)&bqkv, g_bqkv);
    cudaGetSymbolAddress((void**)&wo,  g_wo);

    cudaFuncSetAttribute(mma_gemm<128>,
                         cudaFuncAttributeMaxDynamicSharedMemorySize, SMEM128);
    cudaFuncSetAttribute(flash_attn_kernel,
                         cudaFuncAttributeMaxDynamicSharedMemorySize, FA_SMEM);

    const int D = DMODEL;
    const long DD = (long)D * D;

    // 1) LoRA folds (2 launches) + bias concat + embed  → launch #5 = QKV GEMM
    {
        int nblk = (int)(DEPTH * DD / 4 / 256);
        weff_qkv_kernel<<<3 * nblk, 256>>>(Wq, Aq, Bq, Wk, Ak, Bk, Wv, Av, Bv,
                                           wqkv);
        weff_kernel<<<nblk, 256>>>(Wo, Ao, Bo, wo, DD, 0);
        bias_concat_kernel<<<DEPTH * 3 * D / 256, 256>>>(bq, bk, bv, bqkv);
    }
    embed_kernel<<<NTOK, 256>>>(idx, tok, pos, phase, x);

    // 2) transformer layers
    for (int i = 0; i < DEPTH; i++) {
        const float* wqkv_i = wqkv + (long)i * 3 * DD;
        const float* woi    = wo + (long)i * DD;

        ln_kernel<<<NTOK, 256>>>(x, ln1w + i * D, ln1b + i * D, h);

        // fused QKV: qkv[NTOK, 3072]
        tgemm128(h, D, wqkv_i, D, 1, bqkv + (long)i * 3 * D, nullptr, 0,
                 qkv, 3 * D, NTOK, 3 * D, D, 0);

        // fused attention: scores + causal softmax + AV in one kernel
        flash_attn_kernel<<<dim3(SEQL / 128, BATCH * NHEAD), 256, FA_SMEM>>>(
            qkv, o);

        // x = x + o @ Wo_eff^T + bo
        tgemm128(o, D, woi, D, 1, bo + i * D, x, D, x, D, NTOK, D, D, 0);

        ln_kernel<<<NTOK, 256>>>(x, ln2w + i * D, ln2b + i * D, h);

        // ff = gelu(h @ W1^T + b1)
        tgemm128(h, D, W1 + (long)i * HIDDEN * D, D, 1, b1 + i * HIDDEN,
                 nullptr, 0, ff, HIDDEN, NTOK, HIDDEN, D, /*flags=*/1);
        // x = x + ff @ W2^T + b2
        tgemm128(ff, HIDDEN, W2 + (long)i * D * HIDDEN, HIDDEN, 1, b2 + i * D,
                 x, D, x, D, NTOK, D, HIDDEN, 0);
    }

    // 3) final LN + LM head (grid-swapped for L2 B reuse)
    ln_kernel<<<NTOK, 256>>>(x, lnfw, lnfb, h);
    tgemm128(h, D, headW, D, 1, nullptr, nullptr, 0, out, VOCAB,
             NTOK, VOCAB, D, /*flags=*/16);
}